// round 7
// baseline (speedup 1.0000x reference)
#include <cuda_runtime.h>
#include <cuda.h>
#include <cstdint>
#include <cstddef>

// ---------------------------------------------------------------------------
// Problem constants
// ---------------------------------------------------------------------------
#define B_DIM 16
#define S_DIM 2048
#define D_DIM 128
#define NTILES 16

// exp(x) = exp2(x*log2e); fold log2e/sqrt(128) into Q pre-scale
#define CQ_SCALE ((float)(1.4426950408889634 / 11.313708498984761))

// SMEM: [0,512) rowsum f32[128]; [512] mbarrier; buffers at 1024
#define QBUF_OFF 1024
#define KBUF_OFF (1024 + 65536)
#define VBUF_OFF (1024 + 131072)
#define SMEM_BYTES (1024 + 196608)

// ---------------------------------------------------------------------------
// Device scratch (static; no allocations allowed)
// ---------------------------------------------------------------------------
__device__ float g_Qr[B_DIM * S_DIM * D_DIM];                 // Q*(log2e/sqrt d), tf32-rounded
__device__ float g_Kr[B_DIM * S_DIM * D_DIM];                 // K tf32-rounded
__device__ float g_VT[B_DIM * D_DIM * S_DIM];                 // V^T [b][d][s], tf32-rounded
__device__ unsigned long long g_Mb[B_DIM * S_DIM * (S_DIM / 64)];  // mask bitpack
__device__ int g_mask_elem4;                                  // 1 if mask elements are 4-byte

// ---------------------------------------------------------------------------
// PTX helpers
// ---------------------------------------------------------------------------
__device__ __forceinline__ uint32_t smem_u32(const void* p) {
    uint32_t a;
    asm("{ .reg .u64 t; cvta.to.shared.u64 t, %1; cvt.u32.u64 %0, t; }" : "=r"(a) : "l"(p));
    return a;
}
// cvt.rna.tf32.f32 requires a .b32 destination register.
__device__ __forceinline__ float rna_tf32(float x) {
    uint32_t r; asm("cvt.rna.tf32.f32 %0, %1;" : "=r"(r) : "f"(x));
    return __uint_as_float(r);
}
__device__ __forceinline__ float ex2f(float x) {
    float r; asm("ex2.approx.f32 %0, %1;" : "=f"(r) : "f"(x)); return r;
}

#define MBAR_INIT(a, c) \
    asm volatile("mbarrier.init.shared.b64 [%0], %1;" :: "r"(a), "r"((uint32_t)(c)) : "memory")
#define MBAR_EXPECT_TX(a, n) \
    asm volatile("mbarrier.arrive.expect_tx.shared.b64 _, [%0], %1;" :: "r"(a), "r"((uint32_t)(n)) : "memory")

#define MBAR_WAIT(a, ph) do {                                                     \
    uint32_t _m = (a), _p = (uint32_t)(ph), _d;                                   \
    asm volatile("{\n\t.reg .pred p;\n\t"                                         \
        "mbarrier.try_wait.parity.acquire.cta.shared::cta.b64 p, [%1], %2;\n\t"   \
        "selp.b32 %0, 1, 0, p;\n\t}"                                              \
        : "=r"(_d) : "r"(_m), "r"(_p) : "memory");                                \
    if (!_d) {                                                                    \
        asm volatile("{\n\t.reg .pred P1;\n\t"                                    \
            "WL_%=:\n\t"                                                          \
            "mbarrier.try_wait.parity.acquire.cta.shared::cta.b64 P1, [%0], %1, 0x989680;\n\t" \
            "@P1 bra.uni WD_%=;\n\t"                                              \
            "bra.uni WL_%=;\n\t"                                                  \
            "WD_%=:\n\t}"                                                         \
            :: "r"(_m), "r"(_p) : "memory");                                      \
    }                                                                             \
} while (0)

#define TMA3D(dst, map, x, y, z, mb)                                              \
    asm volatile("cp.async.bulk.tensor.3d.shared::cta.global.tile.mbarrier::complete_tx::bytes " \
                 "[%0], [%1, {%2, %3, %4}], [%5];"                                \
                 :: "r"(dst), "l"(map), "r"((int)(x)), "r"((int)(y)), "r"((int)(z)), "r"(mb) : "memory")

// Swizzled address of f32 element (row, col) in a tile stored as four 16KB
// regions (32 f32-cols each), 128B rows, TMA SW128 swizzle.
__device__ __forceinline__ uint32_t swa(uint32_t buf, int row, int col) {
    uint32_t byte = (uint32_t)(row * 128 + (col & 31) * 4);
    return buf + (((uint32_t)col >> 5) << 14) + (byte ^ ((byte >> 3) & 0x70));
}

__device__ __forceinline__ void ldsm4(uint32_t addr, uint32_t* r) {
    asm volatile("ldmatrix.sync.aligned.m8n8.x4.shared.b16 {%0,%1,%2,%3}, [%4];"
                 : "=r"(r[0]), "=r"(r[1]), "=r"(r[2]), "=r"(r[3]) : "r"(addr));
}

__device__ __forceinline__ void mma8(float* c, const uint32_t* a, uint32_t b0, uint32_t b1) {
    asm volatile("mma.sync.aligned.m16n8k8.row.col.f32.tf32.tf32.f32 "
                 "{%0,%1,%2,%3}, {%4,%5,%6,%7}, {%8,%9}, {%0,%1,%2,%3};"
                 : "+f"(c[0]), "+f"(c[1]), "+f"(c[2]), "+f"(c[3])
                 : "r"(a[0]), "r"(a[1]), "r"(a[2]), "r"(a[3]), "r"(b0), "r"(b1));
}

__device__ __forceinline__ void sts2(uint32_t addr, float x, float y) {
    asm volatile("st.shared.v2.f32 [%0], {%1,%2};" :: "r"(addr), "f"(x), "f"(y) : "memory");
}

// ---------------------------------------------------------------------------
// Prep kernels
// ---------------------------------------------------------------------------
__global__ void prep_qk(const float4* __restrict__ q, const float4* __restrict__ k,
                        float4* __restrict__ qo, float4* __restrict__ ko) {
    int i = blockIdx.x * blockDim.x + threadIdx.x;
    float4 a = q[i];
    a.x = rna_tf32(a.x * CQ_SCALE); a.y = rna_tf32(a.y * CQ_SCALE);
    a.z = rna_tf32(a.z * CQ_SCALE); a.w = rna_tf32(a.w * CQ_SCALE);
    qo[i] = a;
    float4 b = k[i];
    b.x = rna_tf32(b.x); b.y = rna_tf32(b.y);
    b.z = rna_tf32(b.z); b.w = rna_tf32(b.w);
    ko[i] = b;
}

// V [b][s][d] -> VT [b][d][s], tf32-rounded
__global__ void prep_vt(const float* __restrict__ v, float* __restrict__ vt) {
    __shared__ float t[32][33];
    int b = blockIdx.z;
    int s0 = blockIdx.x * 32, d0 = blockIdx.y * 32;
    const float* vb = v + (size_t)b * S_DIM * D_DIM;
    float* vtb = vt + (size_t)b * D_DIM * S_DIM;
    t[threadIdx.y][threadIdx.x] =
        rna_tf32(vb[(size_t)(s0 + threadIdx.y) * D_DIM + d0 + threadIdx.x]);
    __syncthreads();
    vtb[(size_t)(d0 + threadIdx.y) * S_DIM + s0 + threadIdx.x] = t[threadIdx.x][threadIdx.y];
}

// --- Mask dtype detection -------------------------------------------------
// Sample 4096 u32 words. 4-byte-element masks (int32 0/1 or f32 0.0/1.0) only
// produce words in {0, 1, 0x3F800000}. A 1-byte mask produces a word in that
// set with prob 1/8 -> all 4096 in-set is impossible for byte data.
__global__ void detect_mask(const uint32_t* __restrict__ m) {
    __shared__ int bad;
    if (threadIdx.x == 0) bad = 0;
    __syncthreads();
    for (int i = threadIdx.x; i < 4096; i += blockDim.x) {
        uint32_t w = m[i];
        if (w != 0u && w != 1u && w != 0x3F800000u) bad = 1;
    }
    __syncthreads();
    if (threadIdx.x == 0) g_mask_elem4 = bad ? 0 : 1;
}

// Produce the mask bitpack as bytes: out byte i <- mask elements [8i, 8i+8).
// Bit j of byte i corresponds to element 8i+j (little-endian across the u64).
__global__ void prep_mask(const void* __restrict__ m, unsigned char* __restrict__ o) {
    int i = blockIdx.x * blockDim.x + threadIdx.x;
    unsigned v;
    if (g_mask_elem4) {
        const uint4* p = (const uint4*)m + (size_t)i * 2;
        uint4 a = p[0], b = p[1];
        v = (a.x != 0u ? 1u : 0u) | (a.y != 0u ? 2u : 0u) |
            (a.z != 0u ? 4u : 0u) | (a.w != 0u ? 8u : 0u) |
            (b.x != 0u ? 16u : 0u) | (b.y != 0u ? 32u : 0u) |
            (b.z != 0u ? 64u : 0u) | (b.w != 0u ? 128u : 0u);
    } else {
        uint2 w = ((const uint2*)m)[i];
        // nonzero-byte -> bit, robust to 0x01 or 0xFF encodings
        uint32_t lo = __vcmpne4(w.x, 0u) & 0x01010101u;
        uint32_t hi = __vcmpne4(w.y, 0u) & 0x01010101u;
        uint32_t nlo = ((lo * 0x01020408u) >> 24) & 0xFu;
        uint32_t nhi = ((hi * 0x01020408u) >> 24) & 0xFu;
        v = nlo | (nhi << 4);
    }
    o[i] = (unsigned char)v;
}

// ---------------------------------------------------------------------------
// Main fused attention kernel.
// 1 CTA = (batch, 128-row q-tile); 8 warps: mchunk = wid&3 (32 q-rows),
// half = wid>>2 (64-col n/d half). mma.sync m16n8k8 tf32 throughout.
// ---------------------------------------------------------------------------
__global__ void __launch_bounds__(256, 1) attn_main(
    const __grid_constant__ CUtensorMap qmap,
    const __grid_constant__ CUtensorMap kmap,
    const __grid_constant__ CUtensorMap vmap,
    const unsigned long long* __restrict__ mbits,
    float* __restrict__ out)
{
    extern __shared__ char smem[];
    float* rs = (float*)smem;               // rowsum[128]
    const uint32_t sb = smem_u32(smem);
    const uint32_t mb = sb + 512;
    const uint32_t QBUF = sb + QBUF_OFF, KBUF = sb + KBUF_OFF, VBUF = sb + VBUF_OFF;

    const int tid = threadIdx.x, wid = tid >> 5, lane = tid & 31;
    const int mchunk = wid & 3, half = wid >> 2;
    const int tig = lane & 3, g = lane >> 2;
    const int b = blockIdx.x >> 4, qt = blockIdx.x & 15;

    // ldmatrix lane-role rows (address supply): A rows and B rows
    const int arow0 = 32 * mchunk + (lane & 7) + ((lane >> 3) & 1) * 8;   // + 16*mi
    const int brow0 = 64 * half + (lane & 7) + ((lane >> 4) & 1) * 8;     // + 16*nbp
    const int acsel = ((lane >> 4) & 1) * 4;    // A col offset within k8
    const int bcsel = ((lane >> 3) & 1) * 4;    // B col offset within k8

    if (tid < 128) rs[tid] = 0.0f;
    if (tid == 0) MBAR_INIT(mb, 1);
    __syncthreads();

    // Issue Q + K(0) + V(0)
    if (tid == 0) {
        MBAR_EXPECT_TX(mb, 196608);
#pragma unroll
        for (int c = 0; c < 4; c++) {
            TMA3D(QBUF + c * 16384, &qmap, 32 * c, qt * 128, b, mb);
            TMA3D(KBUF + c * 16384, &kmap, 32 * c, 0, b, mb);
            TMA3D(VBUF + c * 16384, &vmap, 32 * c, 0, b, mb);
        }
    }

    float oacc[2][8][4];
#pragma unroll
    for (int mi = 0; mi < 2; mi++)
#pragma unroll
        for (int nb = 0; nb < 8; nb++)
#pragma unroll
            for (int i = 0; i < 4; i++) oacc[mi][nb][i] = 0.0f;

    float rsum[4] = {0.f, 0.f, 0.f, 0.f};
    const size_t mrow_base = ((size_t)b * S_DIM + qt * 128) * (S_DIM / 64);
    int tp = 0;

    for (int j = 0; j < NTILES; j++) {
        // Mask u64s for this tile (issued before the TMA wait to hide latency)
        unsigned long long mrow[4];
#pragma unroll
        for (int mi = 0; mi < 2; mi++) {
            int r = 32 * mchunk + 16 * mi + g;
            mrow[2 * mi]     = __ldg(mbits + mrow_base + (size_t)r * 32 + 2 * j + half);
            mrow[2 * mi + 1] = __ldg(mbits + mrow_base + (size_t)(r + 8) * 32 + 2 * j + half);
        }

        MBAR_WAIT(mb, tp); tp ^= 1;

        // ---- S-phase: S = Q @ K^T over d (16 k8-steps) ----
        float sacc[2][8][4];
#pragma unroll
        for (int mi = 0; mi < 2; mi++)
#pragma unroll
            for (int nb = 0; nb < 8; nb++)
#pragma unroll
                for (int i = 0; i < 4; i++) sacc[mi][nb][i] = 0.0f;

#pragma unroll 4
        for (int kk = 0; kk < 16; kk++) {
            uint32_t a0[4], a1[4], bb[4][4];
            ldsm4(swa(QBUF, arow0,      8 * kk + acsel), a0);
            ldsm4(swa(QBUF, arow0 + 16, 8 * kk + acsel), a1);
#pragma unroll
            for (int nbp = 0; nbp < 4; nbp++)
                ldsm4(swa(KBUF, brow0 + 16 * nbp, 8 * kk + bcsel), bb[nbp]);
#pragma unroll
            for (int nbp = 0; nbp < 4; nbp++) {
                mma8(sacc[0][2 * nbp],     a0, bb[nbp][0], bb[nbp][1]);
                mma8(sacc[0][2 * nbp + 1], a0, bb[nbp][2], bb[nbp][3]);
                mma8(sacc[1][2 * nbp],     a1, bb[nbp][0], bb[nbp][1]);
                mma8(sacc[1][2 * nbp + 1], a1, bb[nbp][2], bb[nbp][3]);
            }
        }

        __syncthreads();   // all warps done reading K before P overwrites it

        // ---- exp + mask; write P (tf32-rounded) into KBUF; row-sum ----
#pragma unroll
        for (int mi = 0; mi < 2; mi++) {
            int r0 = 32 * mchunk + 16 * mi + g;
#pragma unroll
            for (int nb = 0; nb < 8; nb++) {
                float* c = sacc[mi][nb];
                unsigned sh = 8 * nb + 2 * tig;
                unsigned m0 = (unsigned)(mrow[2 * mi] >> sh) & 3u;
                unsigned m1 = (unsigned)(mrow[2 * mi + 1] >> sh) & 3u;
                float p0 = (m0 & 1u) ? 0.f : rna_tf32(ex2f(c[0]));
                float p1 = (m0 & 2u) ? 0.f : rna_tf32(ex2f(c[1]));
                float p2 = (m1 & 1u) ? 0.f : rna_tf32(ex2f(c[2]));
                float p3 = (m1 & 2u) ? 0.f : rna_tf32(ex2f(c[3]));
                rsum[2 * mi]     += p0 + p1;
                rsum[2 * mi + 1] += p2 + p3;
                int cl = 64 * half + 8 * nb + 2 * tig;
                sts2(swa(KBUF, r0,     cl), p0, p1);
                sts2(swa(KBUF, r0 + 8, cl), p2, p3);
            }
        }
        __syncthreads();   // P visible to all warps

        // ---- O-phase: O += P @ V (A = P from KBUF, B = V^T tile in VBUF) ----
#pragma unroll 4
        for (int kk = 0; kk < 16; kk++) {
            uint32_t a0[4], a1[4], bb[4][4];
            ldsm4(swa(KBUF, arow0,      8 * kk + acsel), a0);
            ldsm4(swa(KBUF, arow0 + 16, 8 * kk + acsel), a1);
#pragma unroll
            for (int nbp = 0; nbp < 4; nbp++)
                ldsm4(swa(VBUF, brow0 + 16 * nbp, 8 * kk + bcsel), bb[nbp]);
#pragma unroll
            for (int nbp = 0; nbp < 4; nbp++) {
                mma8(oacc[0][2 * nbp],     a0, bb[nbp][0], bb[nbp][1]);
                mma8(oacc[0][2 * nbp + 1], a0, bb[nbp][2], bb[nbp][3]);
                mma8(oacc[1][2 * nbp],     a1, bb[nbp][0], bb[nbp][1]);
                mma8(oacc[1][2 * nbp + 1], a1, bb[nbp][2], bb[nbp][3]);
            }
        }
        __syncthreads();   // all warps done with KBUF(P)/VBUF

        if (tid == 0 && j < NTILES - 1) {
            MBAR_EXPECT_TX(mb, 131072);
#pragma unroll
            for (int c = 0; c < 4; c++) {
                TMA3D(KBUF + c * 16384, &kmap, 32 * c, (j + 1) * 128, b, mb);
                TMA3D(VBUF + c * 16384, &vmap, (j + 1) * 128 + 32 * c, 0, b, mb);
            }
        }
    }

    // ---- Row sums: reduce over tig, combine halves via smem atomics ----
#pragma unroll
    for (int i = 0; i < 4; i++) {
        rsum[i] += __shfl_xor_sync(0xffffffffu, rsum[i], 1);
        rsum[i] += __shfl_xor_sync(0xffffffffu, rsum[i], 2);
    }
    if (tig == 0) {
#pragma unroll
        for (int mi = 0; mi < 2; mi++) {
            atomicAdd(&rs[32 * mchunk + 16 * mi + g],     rsum[2 * mi]);
            atomicAdd(&rs[32 * mchunk + 16 * mi + g + 8], rsum[2 * mi + 1]);
        }
    }
    __syncthreads();

    // ---- Normalize + store O ----
    const size_t obase = ((size_t)b * S_DIM + qt * 128) * D_DIM;
#pragma unroll
    for (int mi = 0; mi < 2; mi++) {
        int r0 = 32 * mchunk + 16 * mi + g;
        float inv0 = 1.0f / rs[r0];
        float inv1 = 1.0f / rs[r0 + 8];
#pragma unroll
        for (int di = 0; di < 8; di++) {
            int col = 64 * half + 8 * di + 2 * tig;
            float* c = oacc[mi][di];
            float2* p0 = (float2*)(out + obase + (size_t)r0 * D_DIM + col);
            float2* p1 = (float2*)(out + obase + (size_t)(r0 + 8) * D_DIM + col);
            *p0 = make_float2(c[0] * inv0, c[1] * inv0);
            *p1 = make_float2(c[2] * inv1, c[3] * inv1);
        }
    }
}

// ---------------------------------------------------------------------------
// Host launcher
// ---------------------------------------------------------------------------
typedef CUresult (*EncodeFn)(CUtensorMap*, CUtensorMapDataType, cuuint32_t, void*,
                             const cuuint64_t*, const cuuint64_t*, const cuuint32_t*,
                             const cuuint32_t*, CUtensorMapInterleave, CUtensorMapSwizzle,
                             CUtensorMapL2promotion, CUtensorMapFloatOOBfill);

static void make_map(EncodeFn enc, CUtensorMap* m, void* ptr,
                     cuuint64_t d0, cuuint64_t d1, cuuint64_t d2) {
    cuuint64_t dims[3] = {d0, d1, d2};
    cuuint64_t strides[2] = {d0 * 4, d0 * d1 * 4};
    cuuint32_t box[3] = {32, 128, 1};
    cuuint32_t es[3] = {1, 1, 1};
    enc(m, CU_TENSOR_MAP_DATA_TYPE_FLOAT32, 3, ptr, dims, strides, box, es,
        CU_TENSOR_MAP_INTERLEAVE_NONE, CU_TENSOR_MAP_SWIZZLE_128B,
        CU_TENSOR_MAP_L2_PROMOTION_L2_128B, CU_TENSOR_MAP_FLOAT_OOB_FILL_NONE);
}

extern "C" void kernel_launch(void* const* d_in, const int* in_sizes, int n_in,
                              void* d_out, int out_size) {
    const float* q = (const float*)d_in[0];
    const float* k = (const float*)d_in[1];
    const float* v = (const float*)d_in[2];
    const void* mask = d_in[3];
    float* out = (float*)d_out;

    void *qr = 0, *kr = 0, *vt = 0, *mbp = 0;
    cudaGetSymbolAddress(&qr, g_Qr);
    cudaGetSymbolAddress(&kr, g_Kr);
    cudaGetSymbolAddress(&vt, g_VT);
    cudaGetSymbolAddress(&mbp, g_Mb);

    void* fptr = 0;
    cudaDriverEntryPointQueryResult qres;
    cudaGetDriverEntryPointByVersion("cuTensorMapEncodeTiled", &fptr, 12000,
                                     cudaEnableDefault, &qres);
    EncodeFn enc = (EncodeFn)fptr;
    if (!enc) return;

    CUtensorMap qmap, kmap, vmap;
    make_map(enc, &qmap, qr, D_DIM, S_DIM, B_DIM);   // [b][s][d], box 32d x 128s
    make_map(enc, &kmap, kr, D_DIM, S_DIM, B_DIM);
    make_map(enc, &vmap, vt, S_DIM, D_DIM, B_DIM);   // [b][d][s], box 32s x 128d

    // Prep passes
    int n4 = (B_DIM * S_DIM * D_DIM) / 4;                 // 1,048,576
    prep_qk<<<n4 / 256, 256>>>((const float4*)q, (const float4*)k, (float4*)qr, (float4*)kr);
    prep_vt<<<dim3(S_DIM / 32, D_DIM / 32, B_DIM), dim3(32, 32)>>>(v, (float*)vt);

    detect_mask<<<1, 256>>>((const uint32_t*)mask);
    int nmb = (B_DIM * S_DIM * S_DIM) / 8;                // 8,388,608 output bytes
    prep_mask<<<nmb / 256, 256>>>(mask, (unsigned char*)mbp);

    cudaFuncSetAttribute(attn_main, cudaFuncAttributeMaxDynamicSharedMemorySize, SMEM_BYTES);
    attn_main<<<B_DIM * 16, 256, SMEM_BYTES>>>(qmap, kmap, vmap,
                                               (const unsigned long long*)mbp, out);
}

// round 8
// speedup vs baseline: 1.0458x; 1.0458x over previous
#include <cuda_runtime.h>
#include <cuda.h>
#include <cstdint>
#include <cstddef>

// ---------------------------------------------------------------------------
// Problem constants
// ---------------------------------------------------------------------------
#define B_DIM 16
#define S_DIM 2048
#define D_DIM 128
#define NT2 32            // 64-row k-tiles

// exp(x) = exp2(x*log2e); fold log2e/sqrt(128) into Q pre-scale
#define CQ_SCALE ((float)(1.4426950408889634 / 11.313708498984761))

// SMEM layout: [0,512) rowsum f32[128]; [512..544) mbarriers; buffers at 1024
// QBUF 64K | KB0 32K | KB1 32K | VB0 32K | VB1 32K | PBUF 32K
#define QBUF_OFF 1024
#define KB0_OFF  (1024 + 65536)
#define KB1_OFF  (KB0_OFF + 32768)
#define VB0_OFF  (KB1_OFF + 32768)
#define VB1_OFF  (VB0_OFF + 32768)
#define PBUF_OFF (VB1_OFF + 32768)
#define SMEM_BYTES (PBUF_OFF + 32768)   // 230400

// ---------------------------------------------------------------------------
// Device scratch (static; no allocations allowed)
// ---------------------------------------------------------------------------
__device__ float g_Qr[B_DIM * S_DIM * D_DIM];                 // Q*(log2e/sqrt d), tf32-rounded
__device__ float g_Kr[B_DIM * S_DIM * D_DIM];                 // K tf32-rounded
__device__ float g_VT[B_DIM * D_DIM * S_DIM];                 // V^T [b][d][s], tf32-rounded
__device__ unsigned long long g_Mb[B_DIM * S_DIM * (S_DIM / 64)];  // mask bitpack
__device__ int g_mask_elem4;                                  // 1 if mask elements are 4-byte

// ---------------------------------------------------------------------------
// PTX helpers
// ---------------------------------------------------------------------------
__device__ __forceinline__ uint32_t smem_u32(const void* p) {
    uint32_t a;
    asm("{ .reg .u64 t; cvta.to.shared.u64 t, %1; cvt.u32.u64 %0, t; }" : "=r"(a) : "l"(p));
    return a;
}
// cvt.rna.tf32.f32 requires a .b32 destination register.
__device__ __forceinline__ float rna_tf32(float x) {
    uint32_t r; asm("cvt.rna.tf32.f32 %0, %1;" : "=r"(r) : "f"(x));
    return __uint_as_float(r);
}
__device__ __forceinline__ float ex2f(float x) {
    float r; asm("ex2.approx.f32 %0, %1;" : "=f"(r) : "f"(x)); return r;
}

#define MBAR_INIT(a, c) \
    asm volatile("mbarrier.init.shared.b64 [%0], %1;" :: "r"(a), "r"((uint32_t)(c)) : "memory")
#define MBAR_EXPECT_TX(a, n) \
    asm volatile("mbarrier.arrive.expect_tx.shared.b64 _, [%0], %1;" :: "r"(a), "r"((uint32_t)(n)) : "memory")

#define MBAR_WAIT(a, ph) do {                                                     \
    uint32_t _m = (a), _p = (uint32_t)(ph), _d;                                   \
    asm volatile("{\n\t.reg .pred p;\n\t"                                         \
        "mbarrier.try_wait.parity.acquire.cta.shared::cta.b64 p, [%1], %2;\n\t"   \
        "selp.b32 %0, 1, 0, p;\n\t}"                                              \
        : "=r"(_d) : "r"(_m), "r"(_p) : "memory");                                \
    if (!_d) {                                                                    \
        asm volatile("{\n\t.reg .pred P1;\n\t"                                    \
            "WL_%=:\n\t"                                                          \
            "mbarrier.try_wait.parity.acquire.cta.shared::cta.b64 P1, [%0], %1, 0x989680;\n\t" \
            "@P1 bra.uni WD_%=;\n\t"                                              \
            "bra.uni WL_%=;\n\t"                                                  \
            "WD_%=:\n\t}"                                                         \
            :: "r"(_m), "r"(_p) : "memory");                                      \
    }                                                                             \
} while (0)

#define TMA3D(dst, map, x, y, z, mb)                                              \
    asm volatile("cp.async.bulk.tensor.3d.shared::cta.global.tile.mbarrier::complete_tx::bytes " \
                 "[%0], [%1, {%2, %3, %4}], [%5];"                                \
                 :: "r"(dst), "l"(map), "r"((int)(x)), "r"((int)(y)), "r"((int)(z)), "r"(mb) : "memory")

// Swizzled address of f32 element (row, col): region = 32 f32-cols wide,
// rows*128B tall; rshift = log2(region bytes). TMA SW128 swizzle inside.
__device__ __forceinline__ uint32_t swa2(uint32_t buf, int row, int col, int rshift) {
    uint32_t byte = (uint32_t)(row * 128 + (col & 31) * 4);
    return buf + (((uint32_t)col >> 5) << rshift) + (byte ^ ((byte >> 3) & 0x70));
}

__device__ __forceinline__ void ldsm4(uint32_t addr, uint32_t* r) {
    asm volatile("ldmatrix.sync.aligned.m8n8.x4.shared.b16 {%0,%1,%2,%3}, [%4];"
                 : "=r"(r[0]), "=r"(r[1]), "=r"(r[2]), "=r"(r[3]) : "r"(addr));
}

__device__ __forceinline__ void mma8(float* c, const uint32_t* a, uint32_t b0, uint32_t b1) {
    asm volatile("mma.sync.aligned.m16n8k8.row.col.f32.tf32.tf32.f32 "
                 "{%0,%1,%2,%3}, {%4,%5,%6,%7}, {%8,%9}, {%0,%1,%2,%3};"
                 : "+f"(c[0]), "+f"(c[1]), "+f"(c[2]), "+f"(c[3])
                 : "r"(a[0]), "r"(a[1]), "r"(a[2]), "r"(a[3]), "r"(b0), "r"(b1));
}

__device__ __forceinline__ void sts2(uint32_t addr, float x, float y) {
    asm volatile("st.shared.v2.f32 [%0], {%1,%2};" :: "r"(addr), "f"(x), "f"(y) : "memory");
}

// ---------------------------------------------------------------------------
// Prep kernels (unchanged from passing R7 kernel)
// ---------------------------------------------------------------------------
__global__ void prep_qk(const float4* __restrict__ q, const float4* __restrict__ k,
                        float4* __restrict__ qo, float4* __restrict__ ko) {
    int i = blockIdx.x * blockDim.x + threadIdx.x;
    float4 a = q[i];
    a.x = rna_tf32(a.x * CQ_SCALE); a.y = rna_tf32(a.y * CQ_SCALE);
    a.z = rna_tf32(a.z * CQ_SCALE); a.w = rna_tf32(a.w * CQ_SCALE);
    qo[i] = a;
    float4 b = k[i];
    b.x = rna_tf32(b.x); b.y = rna_tf32(b.y);
    b.z = rna_tf32(b.z); b.w = rna_tf32(b.w);
    ko[i] = b;
}

__global__ void prep_vt(const float* __restrict__ v, float* __restrict__ vt) {
    __shared__ float t[32][33];
    int b = blockIdx.z;
    int s0 = blockIdx.x * 32, d0 = blockIdx.y * 32;
    const float* vb = v + (size_t)b * S_DIM * D_DIM;
    float* vtb = vt + (size_t)b * D_DIM * S_DIM;
    t[threadIdx.y][threadIdx.x] =
        rna_tf32(vb[(size_t)(s0 + threadIdx.y) * D_DIM + d0 + threadIdx.x]);
    __syncthreads();
    vtb[(size_t)(d0 + threadIdx.y) * S_DIM + s0 + threadIdx.x] = t[threadIdx.x][threadIdx.y];
}

__global__ void detect_mask(const uint32_t* __restrict__ m) {
    __shared__ int bad;
    if (threadIdx.x == 0) bad = 0;
    __syncthreads();
    for (int i = threadIdx.x; i < 4096; i += blockDim.x) {
        uint32_t w = m[i];
        if (w != 0u && w != 1u && w != 0x3F800000u) bad = 1;
    }
    __syncthreads();
    if (threadIdx.x == 0) g_mask_elem4 = bad ? 0 : 1;
}

__global__ void prep_mask(const void* __restrict__ m, unsigned char* __restrict__ o) {
    int i = blockIdx.x * blockDim.x + threadIdx.x;
    unsigned v;
    if (g_mask_elem4) {
        const uint4* p = (const uint4*)m + (size_t)i * 2;
        uint4 a = p[0], b = p[1];
        v = (a.x != 0u ? 1u : 0u) | (a.y != 0u ? 2u : 0u) |
            (a.z != 0u ? 4u : 0u) | (a.w != 0u ? 8u : 0u) |
            (b.x != 0u ? 16u : 0u) | (b.y != 0u ? 32u : 0u) |
            (b.z != 0u ? 64u : 0u) | (b.w != 0u ? 128u : 0u);
    } else {
        uint2 w = ((const uint2*)m)[i];
        uint32_t lo = __vcmpne4(w.x, 0u) & 0x01010101u;
        uint32_t hi = __vcmpne4(w.y, 0u) & 0x01010101u;
        uint32_t nlo = ((lo * 0x01020408u) >> 24) & 0xFu;
        uint32_t nhi = ((hi * 0x01020408u) >> 24) & 0xFu;
        v = nlo | (nhi << 4);
    }
    o[i] = (unsigned char)v;
}

// ---------------------------------------------------------------------------
// Main fused attention kernel — double-buffered 64-row k-tiles.
// 1 CTA = (batch, 128-row q-tile); 8 warps: mchunk = wid&3 (32 q-rows),
// half = wid>>2. S-phase: warp = 32m x 32n. O-phase: warp = 32m x 64d.
// ---------------------------------------------------------------------------
__global__ void __launch_bounds__(256, 1) attn_main(
    const __grid_constant__ CUtensorMap qmap,
    const __grid_constant__ CUtensorMap kmap,   // box {32,64}
    const __grid_constant__ CUtensorMap vmap,   // box {32,128}
    const unsigned long long* __restrict__ mbits,
    float* __restrict__ out)
{
    extern __shared__ char smem[];
    float* rs = (float*)smem;               // rowsum[128]
    const uint32_t sb = smem_u32(smem);
    const uint32_t kbar0 = sb + 512, kbar1 = sb + 520;
    const uint32_t vbar0 = sb + 528, vbar1 = sb + 536;
    const uint32_t QBUF = sb + QBUF_OFF, PBUF = sb + PBUF_OFF;
    const uint32_t KB[2] = {sb + KB0_OFF, sb + KB1_OFF};
    const uint32_t VB[2] = {sb + VB0_OFF, sb + VB1_OFF};

    const int tid = threadIdx.x, wid = tid >> 5, lane = tid & 31;
    const int mchunk = wid & 3, half = wid >> 2;
    const int tig = lane & 3, g = lane >> 2;
    const int b = blockIdx.x >> 4, qt = blockIdx.x & 15;

    // ldmatrix lane-role rows
    const int arow0  = 32 * mchunk + (lane & 7) + ((lane >> 3) & 1) * 8;  // A rows (+16*mi)
    const int brow_s = 32 * half + (lane & 7) + ((lane >> 4) & 1) * 8;    // S-phase B (+16*nbp, nbp<2)
    const int brow_o = 64 * half + (lane & 7) + ((lane >> 4) & 1) * 8;    // O-phase B (+16*nbp, nbp<4)
    const int acsel = ((lane >> 4) & 1) * 4;
    const int bcsel = ((lane >> 3) & 1) * 4;

    if (tid < 128) rs[tid] = 0.0f;
    if (tid == 0) {
        MBAR_INIT(kbar0, 1); MBAR_INIT(kbar1, 1);
        MBAR_INIT(vbar0, 1); MBAR_INIT(vbar1, 1);
    }
    __syncthreads();

    // Prologue: Q + K(0) on kbar0; V(0) on vbar0
    if (tid == 0) {
        MBAR_EXPECT_TX(kbar0, 65536 + 32768);
#pragma unroll
        for (int c = 0; c < 4; c++) {
            TMA3D(QBUF + c * 16384, &qmap, 32 * c, qt * 128, b, kbar0);
            TMA3D(KB[0] + c * 8192, &kmap, 32 * c, 0, b, kbar0);
        }
        MBAR_EXPECT_TX(vbar0, 32768);
#pragma unroll
        for (int c = 0; c < 2; c++)
            TMA3D(VB[0] + c * 16384, &vmap, 32 * c, 0, b, vbar0);
    }

    float oacc[2][8][4];
#pragma unroll
    for (int mi = 0; mi < 2; mi++)
#pragma unroll
        for (int nb = 0; nb < 8; nb++)
#pragma unroll
            for (int i = 0; i < 4; i++) oacc[mi][nb][i] = 0.0f;

    float rsum[4] = {0.f, 0.f, 0.f, 0.f};
    const size_t mrow_base = ((size_t)b * S_DIM + qt * 128) * (S_DIM / 64);

    for (int j = 0; j < NT2; j++) {
        const int bi = j & 1, ni = bi ^ 1;
        const int ph = (j >> 1) & 1;                  // parity of both bars at tile j
        const uint32_t kb = bi ? kbar1 : kbar0;
        const uint32_t vb = bi ? vbar1 : vbar0;

        // Prefetch next tile's K/V into alternate buffers (overlaps all compute)
        if (tid == 0 && j < NT2 - 1) {
            const uint32_t kbn = ni ? kbar1 : kbar0;
            const uint32_t vbn = ni ? vbar1 : vbar0;
            MBAR_EXPECT_TX(kbn, 32768);
#pragma unroll
            for (int c = 0; c < 4; c++)
                TMA3D(KB[ni] + c * 8192, &kmap, 32 * c, (j + 1) * 64, b, kbn);
            MBAR_EXPECT_TX(vbn, 32768);
#pragma unroll
            for (int c = 0; c < 2; c++)
                TMA3D(VB[ni] + c * 16384, &vmap, (j + 1) * 64 + 32 * c, 0, b, vbn);
        }

        // Mask u64s (issued before barrier wait to hide latency)
        unsigned long long mrow[4];
#pragma unroll
        for (int mi = 0; mi < 2; mi++) {
            int r = 32 * mchunk + 16 * mi + g;
            mrow[2 * mi]     = __ldg(mbits + mrow_base + (size_t)r * 32 + j);
            mrow[2 * mi + 1] = __ldg(mbits + mrow_base + (size_t)(r + 8) * 32 + j);
        }

        MBAR_WAIT(kb, ph);

        // ---- S-phase: S(128x64) = Q @ K(j)^T over d (16 k8-steps) ----
        float sacc[2][4][4];
#pragma unroll
        for (int mi = 0; mi < 2; mi++)
#pragma unroll
            for (int nb = 0; nb < 4; nb++)
#pragma unroll
                for (int i = 0; i < 4; i++) sacc[mi][nb][i] = 0.0f;

#pragma unroll 4
        for (int kk = 0; kk < 16; kk++) {
            uint32_t a0[4], a1[4], bb[2][4];
            ldsm4(swa2(QBUF, arow0,      8 * kk + acsel, 14), a0);
            ldsm4(swa2(QBUF, arow0 + 16, 8 * kk + acsel, 14), a1);
#pragma unroll
            for (int nbp = 0; nbp < 2; nbp++)
                ldsm4(swa2(KB[bi], brow_s + 16 * nbp, 8 * kk + bcsel, 13), bb[nbp]);
#pragma unroll
            for (int nbp = 0; nbp < 2; nbp++) {
                mma8(sacc[0][2 * nbp],     a0, bb[nbp][0], bb[nbp][1]);
                mma8(sacc[0][2 * nbp + 1], a0, bb[nbp][2], bb[nbp][3]);
                mma8(sacc[1][2 * nbp],     a1, bb[nbp][0], bb[nbp][1]);
                mma8(sacc[1][2 * nbp + 1], a1, bb[nbp][2], bb[nbp][3]);
            }
        }

        // ---- exp + mask; write P (tf32-rounded) into PBUF; row-sum ----
        // (no sync needed: PBUF reads of O-phase(j-1) finished at end-of-tile sync)
#pragma unroll
        for (int mi = 0; mi < 2; mi++) {
            int r0 = 32 * mchunk + 16 * mi + g;
#pragma unroll
            for (int nb = 0; nb < 4; nb++) {
                float* c = sacc[mi][nb];
                unsigned sh = 32 * half + 8 * nb + 2 * tig;
                unsigned m0 = (unsigned)(mrow[2 * mi] >> sh) & 3u;
                unsigned m1 = (unsigned)(mrow[2 * mi + 1] >> sh) & 3u;
                float p0 = (m0 & 1u) ? 0.f : rna_tf32(ex2f(c[0]));
                float p1 = (m0 & 2u) ? 0.f : rna_tf32(ex2f(c[1]));
                float p2 = (m1 & 1u) ? 0.f : rna_tf32(ex2f(c[2]));
                float p3 = (m1 & 2u) ? 0.f : rna_tf32(ex2f(c[3]));
                rsum[2 * mi]     += p0 + p1;
                rsum[2 * mi + 1] += p2 + p3;
                int cl = 32 * half + 8 * nb + 2 * tig;
                sts2(swa2(PBUF, r0,     cl, 14), p0, p1);
                sts2(swa2(PBUF, r0 + 8, cl, 14), p2, p3);
            }
        }
        __syncthreads();   // P visible to all warps

        MBAR_WAIT(vb, ph);

        // ---- O-phase: O(128x128) += P(128x64) @ V(j)(64x128) ----
#pragma unroll 4
        for (int kk = 0; kk < 8; kk++) {
            uint32_t a0[4], a1[4], bb[4][4];
            ldsm4(swa2(PBUF, arow0,      8 * kk + acsel, 14), a0);
            ldsm4(swa2(PBUF, arow0 + 16, 8 * kk + acsel, 14), a1);
#pragma unroll
            for (int nbp = 0; nbp < 4; nbp++)
                ldsm4(swa2(VB[bi], brow_o + 16 * nbp, 8 * kk + bcsel, 14), bb[nbp]);
#pragma unroll
            for (int nbp = 0; nbp < 4; nbp++) {
                mma8(oacc[0][2 * nbp],     a0, bb[nbp][0], bb[nbp][1]);
                mma8(oacc[0][2 * nbp + 1], a0, bb[nbp][2], bb[nbp][3]);
                mma8(oacc[1][2 * nbp],     a1, bb[nbp][0], bb[nbp][1]);
                mma8(oacc[1][2 * nbp + 1], a1, bb[nbp][2], bb[nbp][3]);
            }
        }
        __syncthreads();   // protect PBUF (next epilogue) & buffer reuse
    }

    // ---- Row sums: reduce over tig, combine halves via smem atomics ----
#pragma unroll
    for (int i = 0; i < 4; i++) {
        rsum[i] += __shfl_xor_sync(0xffffffffu, rsum[i], 1);
        rsum[i] += __shfl_xor_sync(0xffffffffu, rsum[i], 2);
    }
    if (tig == 0) {
#pragma unroll
        for (int mi = 0; mi < 2; mi++) {
            atomicAdd(&rs[32 * mchunk + 16 * mi + g],     rsum[2 * mi]);
            atomicAdd(&rs[32 * mchunk + 16 * mi + g + 8], rsum[2 * mi + 1]);
        }
    }
    __syncthreads();

    // ---- Normalize + store O ----
    const size_t obase = ((size_t)b * S_DIM + qt * 128) * D_DIM;
#pragma unroll
    for (int mi = 0; mi < 2; mi++) {
        int r0 = 32 * mchunk + 16 * mi + g;
        float inv0 = 1.0f / rs[r0];
        float inv1 = 1.0f / rs[r0 + 8];
#pragma unroll
        for (int di = 0; di < 8; di++) {
            int col = 64 * half + 8 * di + 2 * tig;
            float* c = oacc[mi][di];
            float2* p0 = (float2*)(out + obase + (size_t)r0 * D_DIM + col);
            float2* p1 = (float2*)(out + obase + (size_t)(r0 + 8) * D_DIM + col);
            *p0 = make_float2(c[0] * inv0, c[1] * inv0);
            *p1 = make_float2(c[2] * inv1, c[3] * inv1);
        }
    }
}

// ---------------------------------------------------------------------------
// Host launcher
// ---------------------------------------------------------------------------
typedef CUresult (*EncodeFn)(CUtensorMap*, CUtensorMapDataType, cuuint32_t, void*,
                             const cuuint64_t*, const cuuint64_t*, const cuuint32_t*,
                             const cuuint32_t*, CUtensorMapInterleave, CUtensorMapSwizzle,
                             CUtensorMapL2promotion, CUtensorMapFloatOOBfill);

static void make_map(EncodeFn enc, CUtensorMap* m, void* ptr,
                     cuuint64_t d0, cuuint64_t d1, cuuint64_t d2, cuuint32_t box1) {
    cuuint64_t dims[3] = {d0, d1, d2};
    cuuint64_t strides[2] = {d0 * 4, d0 * d1 * 4};
    cuuint32_t box[3] = {32, box1, 1};
    cuuint32_t es[3] = {1, 1, 1};
    enc(m, CU_TENSOR_MAP_DATA_TYPE_FLOAT32, 3, ptr, dims, strides, box, es,
        CU_TENSOR_MAP_INTERLEAVE_NONE, CU_TENSOR_MAP_SWIZZLE_128B,
        CU_TENSOR_MAP_L2_PROMOTION_L2_128B, CU_TENSOR_MAP_FLOAT_OOB_FILL_NONE);
}

extern "C" void kernel_launch(void* const* d_in, const int* in_sizes, int n_in,
                              void* d_out, int out_size) {
    const float* q = (const float*)d_in[0];
    const float* k = (const float*)d_in[1];
    const float* v = (const float*)d_in[2];
    const void* mask = d_in[3];
    float* out = (float*)d_out;

    void *qr = 0, *kr = 0, *vt = 0, *mbp = 0;
    cudaGetSymbolAddress(&qr, g_Qr);
    cudaGetSymbolAddress(&kr, g_Kr);
    cudaGetSymbolAddress(&vt, g_VT);
    cudaGetSymbolAddress(&mbp, g_Mb);

    void* fptr = 0;
    cudaDriverEntryPointQueryResult qres;
    cudaGetDriverEntryPointByVersion("cuTensorMapEncodeTiled", &fptr, 12000,
                                     cudaEnableDefault, &qres);
    EncodeFn enc = (EncodeFn)fptr;
    if (!enc) return;

    CUtensorMap qmap, kmap, vmap;
    make_map(enc, &qmap, qr, D_DIM, S_DIM, B_DIM, 128);  // Q: box 32d x 128s
    make_map(enc, &kmap, kr, D_DIM, S_DIM, B_DIM, 64);   // K: box 32d x 64s
    make_map(enc, &vmap, vt, S_DIM, D_DIM, B_DIM, 128);  // V^T: box 32s x 128d

    // Prep passes (mask first so skip-N ncu capture can land on attn_main)
    detect_mask<<<1, 256>>>((const uint32_t*)mask);
    int nmb = (B_DIM * S_DIM * S_DIM) / 8;                // 8,388,608 output bytes
    prep_mask<<<nmb / 256, 256>>>(mask, (unsigned char*)mbp);
    int n4 = (B_DIM * S_DIM * D_DIM) / 4;                 // 1,048,576
    prep_qk<<<n4 / 256, 256>>>((const float4*)q, (const float4*)k, (float4*)qr, (float4*)kr);
    prep_vt<<<dim3(S_DIM / 32, D_DIM / 32, B_DIM), dim3(32, 32)>>>(v, (float*)vt);

    cudaFuncSetAttribute(attn_main, cudaFuncAttributeMaxDynamicSharedMemorySize, SMEM_BYTES);
    attn_main<<<B_DIM * 16, 256, SMEM_BYTES>>>(qmap, kmap, vmap,
                                               (const unsigned long long*)mbp, out);
}

// round 9
// speedup vs baseline: 1.0568x; 1.0106x over previous
#include <cuda_runtime.h>
#include <cuda.h>
#include <cstdint>
#include <cstddef>

// ---------------------------------------------------------------------------
// Problem constants
// ---------------------------------------------------------------------------
#define B_DIM 16
#define S_DIM 2048
#define D_DIM 128
#define NT2 32            // 64-row k-tiles

// exp(x) = exp2(x*log2e); fold log2e/sqrt(128) into Q pre-scale
#define CQ_SCALE ((float)(1.4426950408889634 / 11.313708498984761))

// SMEM layout: [0,512) rowsum f32[128]; [512..544) mbarriers; buffers at 1024
// QBUF 64K | KB0 32K | KB1 32K | VB0 32K | VB1 32K | PBUF 32K
#define QBUF_OFF 1024
#define KB0_OFF  (1024 + 65536)
#define KB1_OFF  (KB0_OFF + 32768)
#define VB0_OFF  (KB1_OFF + 32768)
#define VB1_OFF  (VB0_OFF + 32768)
#define PBUF_OFF (VB1_OFF + 32768)
#define SMEM_BYTES (PBUF_OFF + 32768)   // 230400

// ---------------------------------------------------------------------------
// Device scratch (static; no allocations allowed)
// ---------------------------------------------------------------------------
__device__ float g_Qr[B_DIM * S_DIM * D_DIM];                 // Q*(log2e/sqrt d), tf32-rounded
__device__ float g_Kr[B_DIM * S_DIM * D_DIM];                 // K tf32-rounded
__device__ float g_VT[B_DIM * D_DIM * S_DIM];                 // V^T [b][d][s], tf32-rounded
__device__ unsigned long long g_Mb[B_DIM * S_DIM * (S_DIM / 64)];  // mask bitpack

// ---------------------------------------------------------------------------
// PTX helpers
// ---------------------------------------------------------------------------
__device__ __forceinline__ uint32_t smem_u32(const void* p) {
    uint32_t a;
    asm("{ .reg .u64 t; cvta.to.shared.u64 t, %1; cvt.u32.u64 %0, t; }" : "=r"(a) : "l"(p));
    return a;
}
// cvt.rna.tf32.f32 requires a .b32 destination register.
__device__ __forceinline__ float rna_tf32(float x) {
    uint32_t r; asm("cvt.rna.tf32.f32 %0, %1;" : "=r"(r) : "f"(x));
    return __uint_as_float(r);
}
__device__ __forceinline__ float ex2f(float x) {
    float r; asm("ex2.approx.f32 %0, %1;" : "=f"(r) : "f"(x)); return r;
}

#define MBAR_INIT(a, c) \
    asm volatile("mbarrier.init.shared.b64 [%0], %1;" :: "r"(a), "r"((uint32_t)(c)) : "memory")
#define MBAR_EXPECT_TX(a, n) \
    asm volatile("mbarrier.arrive.expect_tx.shared.b64 _, [%0], %1;" :: "r"(a), "r"((uint32_t)(n)) : "memory")

#define MBAR_WAIT(a, ph) do {                                                     \
    uint32_t _m = (a), _p = (uint32_t)(ph), _d;                                   \
    asm volatile("{\n\t.reg .pred p;\n\t"                                         \
        "mbarrier.try_wait.parity.acquire.cta.shared::cta.b64 p, [%1], %2;\n\t"   \
        "selp.b32 %0, 1, 0, p;\n\t}"                                              \
        : "=r"(_d) : "r"(_m), "r"(_p) : "memory");                                \
    if (!_d) {                                                                    \
        asm volatile("{\n\t.reg .pred P1;\n\t"                                    \
            "WL_%=:\n\t"                                                          \
            "mbarrier.try_wait.parity.acquire.cta.shared::cta.b64 P1, [%0], %1, 0x989680;\n\t" \
            "@P1 bra.uni WD_%=;\n\t"                                              \
            "bra.uni WL_%=;\n\t"                                                  \
            "WD_%=:\n\t}"                                                         \
            :: "r"(_m), "r"(_p) : "memory");                                      \
    }                                                                             \
} while (0)

#define TMA3D(dst, map, x, y, z, mb)                                              \
    asm volatile("cp.async.bulk.tensor.3d.shared::cta.global.tile.mbarrier::complete_tx::bytes " \
                 "[%0], [%1, {%2, %3, %4}], [%5];"                                \
                 :: "r"(dst), "l"(map), "r"((int)(x)), "r"((int)(y)), "r"((int)(z)), "r"(mb) : "memory")

// Swizzled address of f32 element (row, col): region = 32 f32-cols wide,
// rows*128B tall; rshift = log2(region bytes). TMA SW128 swizzle inside.
__device__ __forceinline__ uint32_t swa2(uint32_t buf, int row, int col, int rshift) {
    uint32_t byte = (uint32_t)(row * 128 + (col & 31) * 4);
    return buf + (((uint32_t)col >> 5) << rshift) + (byte ^ ((byte >> 3) & 0x70));
}

__device__ __forceinline__ void ldsm4(uint32_t addr, uint32_t* r) {
    asm volatile("ldmatrix.sync.aligned.m8n8.x4.shared.b16 {%0,%1,%2,%3}, [%4];"
                 : "=r"(r[0]), "=r"(r[1]), "=r"(r[2]), "=r"(r[3]) : "r"(addr));
}

__device__ __forceinline__ void mma8(float* c, const uint32_t* a, uint32_t b0, uint32_t b1) {
    asm volatile("mma.sync.aligned.m16n8k8.row.col.f32.tf32.tf32.f32 "
                 "{%0,%1,%2,%3}, {%4,%5,%6,%7}, {%8,%9}, {%0,%1,%2,%3};"
                 : "+f"(c[0]), "+f"(c[1]), "+f"(c[2]), "+f"(c[3])
                 : "r"(a[0]), "r"(a[1]), "r"(a[2]), "r"(a[3]), "r"(b0), "r"(b1));
}

__device__ __forceinline__ void sts2(uint32_t addr, float x, float y) {
    asm volatile("st.shared.v2.f32 [%0], {%1,%2};" :: "r"(addr), "f"(x), "f"(y) : "memory");
}

// ---------------------------------------------------------------------------
// Prep kernels
// ---------------------------------------------------------------------------
__global__ void prep_qk(const float4* __restrict__ q, const float4* __restrict__ k,
                        float4* __restrict__ qo, float4* __restrict__ ko) {
    int i = blockIdx.x * blockDim.x + threadIdx.x;
    float4 a = q[i];
    a.x = rna_tf32(a.x * CQ_SCALE); a.y = rna_tf32(a.y * CQ_SCALE);
    a.z = rna_tf32(a.z * CQ_SCALE); a.w = rna_tf32(a.w * CQ_SCALE);
    qo[i] = a;
    float4 b = k[i];
    b.x = rna_tf32(b.x); b.y = rna_tf32(b.y);
    b.z = rna_tf32(b.z); b.w = rna_tf32(b.w);
    ko[i] = b;
}

__global__ void prep_vt(const float* __restrict__ v, float* __restrict__ vt) {
    __shared__ float t[32][33];
    int b = blockIdx.z;
    int s0 = blockIdx.x * 32, d0 = blockIdx.y * 32;
    const float* vb = v + (size_t)b * S_DIM * D_DIM;
    float* vtb = vt + (size_t)b * D_DIM * S_DIM;
    t[threadIdx.y][threadIdx.x] =
        rna_tf32(vb[(size_t)(s0 + threadIdx.y) * D_DIM + d0 + threadIdx.x]);
    __syncthreads();
    vtb[(size_t)(d0 + threadIdx.y) * S_DIM + s0 + threadIdx.x] = t[threadIdx.x][threadIdx.y];
}

// Mask arrives as 4-byte elements (verified in R7 profile: 264MB DRAM read).
// out byte i <- mask elements [8i, 8i+8); bit j of byte i = element 8i+j.
__global__ void prep_mask(const uint4* __restrict__ m, unsigned char* __restrict__ o) {
    int i = blockIdx.x * blockDim.x + threadIdx.x;
    const uint4* p = m + (size_t)i * 2;
    uint4 a = p[0], b = p[1];
    unsigned v =
        (a.x != 0u ? 1u : 0u) | (a.y != 0u ? 2u : 0u) |
        (a.z != 0u ? 4u : 0u) | (a.w != 0u ? 8u : 0u) |
        (b.x != 0u ? 16u : 0u) | (b.y != 0u ? 32u : 0u) |
        (b.z != 0u ? 64u : 0u) | (b.w != 0u ? 128u : 0u);
    o[i] = (unsigned char)v;
}

// ---------------------------------------------------------------------------
// Main fused attention kernel — double-buffered 64-row k-tiles, 16 warps.
// 1 CTA = (batch, 128-row q-tile); warp: mchunk = wid&7 (16 q-rows),
// half = wid>>3. S-phase: warp = 16m x 32n. O-phase: warp = 16m x 64d.
// ---------------------------------------------------------------------------
__global__ void __launch_bounds__(512, 1) attn_main(
    const __grid_constant__ CUtensorMap qmap,
    const __grid_constant__ CUtensorMap kmap,   // box {32,64}
    const __grid_constant__ CUtensorMap vmap,   // box {32,128}
    const unsigned long long* __restrict__ mbits,
    float* __restrict__ out)
{
    extern __shared__ char smem[];
    float* rs = (float*)smem;               // rowsum[128]
    const uint32_t sb = smem_u32(smem);
    const uint32_t kbar0 = sb + 512, kbar1 = sb + 520;
    const uint32_t vbar0 = sb + 528, vbar1 = sb + 536;
    const uint32_t QBUF = sb + QBUF_OFF, PBUF = sb + PBUF_OFF;
    const uint32_t KB[2] = {sb + KB0_OFF, sb + KB1_OFF};
    const uint32_t VB[2] = {sb + VB0_OFF, sb + VB1_OFF};

    const int tid = threadIdx.x, wid = tid >> 5, lane = tid & 31;
    const int mchunk = wid & 7, half = wid >> 3;
    const int tig = lane & 3, g = lane >> 2;
    const int b = blockIdx.x >> 4, qt = blockIdx.x & 15;

    // ldmatrix lane-role rows
    const int arow0  = 16 * mchunk + (lane & 7) + ((lane >> 3) & 1) * 8;  // A rows (one m16 tile)
    const int brow_s = 32 * half + (lane & 7) + ((lane >> 4) & 1) * 8;    // S-phase B (+16*nbp, nbp<2)
    const int brow_o = 64 * half + (lane & 7) + ((lane >> 4) & 1) * 8;    // O-phase B (+16*nbp, nbp<4)
    const int acsel = ((lane >> 4) & 1) * 4;
    const int bcsel = ((lane >> 3) & 1) * 4;

    if (tid < 128) rs[tid] = 0.0f;
    if (tid == 0) {
        MBAR_INIT(kbar0, 1); MBAR_INIT(kbar1, 1);
        MBAR_INIT(vbar0, 1); MBAR_INIT(vbar1, 1);
    }
    __syncthreads();

    // Prologue: Q + K(0) on kbar0; V(0) on vbar0
    if (tid == 0) {
        MBAR_EXPECT_TX(kbar0, 65536 + 32768);
#pragma unroll
        for (int c = 0; c < 4; c++) {
            TMA3D(QBUF + c * 16384, &qmap, 32 * c, qt * 128, b, kbar0);
            TMA3D(KB[0] + c * 8192, &kmap, 32 * c, 0, b, kbar0);
        }
        MBAR_EXPECT_TX(vbar0, 32768);
#pragma unroll
        for (int c = 0; c < 2; c++)
            TMA3D(VB[0] + c * 16384, &vmap, 32 * c, 0, b, vbar0);
    }

    float oacc[8][4];
#pragma unroll
    for (int nb = 0; nb < 8; nb++)
#pragma unroll
        for (int i = 0; i < 4; i++) oacc[nb][i] = 0.0f;

    float rsum[2] = {0.f, 0.f};
    const size_t mrow_base = ((size_t)b * S_DIM + qt * 128) * (S_DIM / 64);

    for (int j = 0; j < NT2; j++) {
        const int bi = j & 1, ni = bi ^ 1;
        const int ph = (j >> 1) & 1;                  // parity of both bars at tile j
        const uint32_t kb = bi ? kbar1 : kbar0;
        const uint32_t vb = bi ? vbar1 : vbar0;

        // Prefetch next tile's K/V into alternate buffers (overlaps all compute)
        if (tid == 0 && j < NT2 - 1) {
            const uint32_t kbn = ni ? kbar1 : kbar0;
            const uint32_t vbn = ni ? vbar1 : vbar0;
            MBAR_EXPECT_TX(kbn, 32768);
#pragma unroll
            for (int c = 0; c < 4; c++)
                TMA3D(KB[ni] + c * 8192, &kmap, 32 * c, (j + 1) * 64, b, kbn);
            MBAR_EXPECT_TX(vbn, 32768);
#pragma unroll
            for (int c = 0; c < 2; c++)
                TMA3D(VB[ni] + c * 16384, &vmap, (j + 1) * 64 + 32 * c, 0, b, vbn);
        }

        // Mask u64s (issued before barrier wait to hide latency)
        const int r0m = 16 * mchunk + g;
        unsigned long long mrow0 = __ldg(mbits + mrow_base + (size_t)r0m * 32 + j);
        unsigned long long mrow1 = __ldg(mbits + mrow_base + (size_t)(r0m + 8) * 32 + j);

        MBAR_WAIT(kb, ph);

        // ---- S-phase: S(128x64) = Q @ K(j)^T over d (16 k8-steps) ----
        float sacc[4][4];
#pragma unroll
        for (int nb = 0; nb < 4; nb++)
#pragma unroll
            for (int i = 0; i < 4; i++) sacc[nb][i] = 0.0f;

#pragma unroll 8
        for (int kk = 0; kk < 16; kk++) {
            uint32_t a0[4], bb[2][4];
            ldsm4(swa2(QBUF, arow0, 8 * kk + acsel, 14), a0);
#pragma unroll
            for (int nbp = 0; nbp < 2; nbp++)
                ldsm4(swa2(KB[bi], brow_s + 16 * nbp, 8 * kk + bcsel, 13), bb[nbp]);
#pragma unroll
            for (int nbp = 0; nbp < 2; nbp++) {
                mma8(sacc[2 * nbp],     a0, bb[nbp][0], bb[nbp][1]);
                mma8(sacc[2 * nbp + 1], a0, bb[nbp][2], bb[nbp][3]);
            }
        }

        // ---- exp + mask; write P (tf32-rounded) into PBUF; row-sum ----
#pragma unroll
        for (int nb = 0; nb < 4; nb++) {
            float* c = sacc[nb];
            unsigned sh = 32 * half + 8 * nb + 2 * tig;
            unsigned m0 = (unsigned)(mrow0 >> sh) & 3u;
            unsigned m1 = (unsigned)(mrow1 >> sh) & 3u;
            float p0 = (m0 & 1u) ? 0.f : rna_tf32(ex2f(c[0]));
            float p1 = (m0 & 2u) ? 0.f : rna_tf32(ex2f(c[1]));
            float p2 = (m1 & 1u) ? 0.f : rna_tf32(ex2f(c[2]));
            float p3 = (m1 & 2u) ? 0.f : rna_tf32(ex2f(c[3]));
            rsum[0] += p0 + p1;
            rsum[1] += p2 + p3;
            int cl = 32 * half + 8 * nb + 2 * tig;
            sts2(swa2(PBUF, r0m,     cl, 14), p0, p1);
            sts2(swa2(PBUF, r0m + 8, cl, 14), p2, p3);
        }
        __syncthreads();   // P visible to all warps

        MBAR_WAIT(vb, ph);

        // ---- O-phase: O(128x128) += P(128x64) @ V(j)(64x128) ----
#pragma unroll 4
        for (int kk = 0; kk < 8; kk++) {
            uint32_t a0[4], bb[4][4];
            ldsm4(swa2(PBUF, arow0, 8 * kk + acsel, 14), a0);
#pragma unroll
            for (int nbp = 0; nbp < 4; nbp++)
                ldsm4(swa2(VB[bi], brow_o + 16 * nbp, 8 * kk + bcsel, 14), bb[nbp]);
#pragma unroll
            for (int nbp = 0; nbp < 4; nbp++) {
                mma8(oacc[2 * nbp],     a0, bb[nbp][0], bb[nbp][1]);
                mma8(oacc[2 * nbp + 1], a0, bb[nbp][2], bb[nbp][3]);
            }
        }
        __syncthreads();   // protect PBUF (next epilogue) & buffer reuse
    }

    // ---- Row sums: reduce over tig, combine halves via smem atomics ----
    rsum[0] += __shfl_xor_sync(0xffffffffu, rsum[0], 1);
    rsum[0] += __shfl_xor_sync(0xffffffffu, rsum[0], 2);
    rsum[1] += __shfl_xor_sync(0xffffffffu, rsum[1], 1);
    rsum[1] += __shfl_xor_sync(0xffffffffu, rsum[1], 2);
    {
        const int r0m = 16 * mchunk + g;
        if (tig == 0) {
            atomicAdd(&rs[r0m],     rsum[0]);
            atomicAdd(&rs[r0m + 8], rsum[1]);
        }
    }
    __syncthreads();

    // ---- Normalize + store O ----
    const size_t obase = ((size_t)b * S_DIM + qt * 128) * D_DIM;
    {
        const int r0m = 16 * mchunk + g;
        float inv0 = 1.0f / rs[r0m];
        float inv1 = 1.0f / rs[r0m + 8];
#pragma unroll
        for (int di = 0; di < 8; di++) {
            int col = 64 * half + 8 * di + 2 * tig;
            float* c = oacc[di];
            float2* p0 = (float2*)(out + obase + (size_t)r0m * D_DIM + col);
            float2* p1 = (float2*)(out + obase + (size_t)(r0m + 8) * D_DIM + col);
            *p0 = make_float2(c[0] * inv0, c[1] * inv0);
            *p1 = make_float2(c[2] * inv1, c[3] * inv1);
        }
    }
}

// ---------------------------------------------------------------------------
// Host launcher
// ---------------------------------------------------------------------------
typedef CUresult (*EncodeFn)(CUtensorMap*, CUtensorMapDataType, cuuint32_t, void*,
                             const cuuint64_t*, const cuuint64_t*, const cuuint32_t*,
                             const cuuint32_t*, CUtensorMapInterleave, CUtensorMapSwizzle,
                             CUtensorMapL2promotion, CUtensorMapFloatOOBfill);

static void make_map(EncodeFn enc, CUtensorMap* m, void* ptr,
                     cuuint64_t d0, cuuint64_t d1, cuuint64_t d2, cuuint32_t box1) {
    cuuint64_t dims[3] = {d0, d1, d2};
    cuuint64_t strides[2] = {d0 * 4, d0 * d1 * 4};
    cuuint32_t box[3] = {32, box1, 1};
    cuuint32_t es[3] = {1, 1, 1};
    enc(m, CU_TENSOR_MAP_DATA_TYPE_FLOAT32, 3, ptr, dims, strides, box, es,
        CU_TENSOR_MAP_INTERLEAVE_NONE, CU_TENSOR_MAP_SWIZZLE_128B,
        CU_TENSOR_MAP_L2_PROMOTION_L2_128B, CU_TENSOR_MAP_FLOAT_OOB_FILL_NONE);
}

extern "C" void kernel_launch(void* const* d_in, const int* in_sizes, int n_in,
                              void* d_out, int out_size) {
    const float* q = (const float*)d_in[0];
    const float* k = (const float*)d_in[1];
    const float* v = (const float*)d_in[2];
    const void* mask = d_in[3];
    float* out = (float*)d_out;

    void *qr = 0, *kr = 0, *vt = 0, *mbp = 0;
    cudaGetSymbolAddress(&qr, g_Qr);
    cudaGetSymbolAddress(&kr, g_Kr);
    cudaGetSymbolAddress(&vt, g_VT);
    cudaGetSymbolAddress(&mbp, g_Mb);

    void* fptr = 0;
    cudaDriverEntryPointQueryResult qres;
    cudaGetDriverEntryPointByVersion("cuTensorMapEncodeTiled", &fptr, 12000,
                                     cudaEnableDefault, &qres);
    EncodeFn enc = (EncodeFn)fptr;
    if (!enc) return;

    CUtensorMap qmap, kmap, vmap;
    make_map(enc, &qmap, qr, D_DIM, S_DIM, B_DIM, 128);  // Q: box 32d x 128s
    make_map(enc, &kmap, kr, D_DIM, S_DIM, B_DIM, 64);   // K: box 32d x 64s
    make_map(enc, &vmap, vt, S_DIM, D_DIM, B_DIM, 128);  // V^T: box 32s x 128d

    // Prep passes (3 before attn_main so ncu's capture slot lands on attn_main)
    int nmb = (B_DIM * S_DIM * S_DIM) / 8;                // 8,388,608 output bytes
    prep_mask<<<nmb / 256, 256>>>((const uint4*)mask, (unsigned char*)mbp);
    int n4 = (B_DIM * S_DIM * D_DIM) / 4;                 // 1,048,576
    prep_qk<<<n4 / 256, 256>>>((const float4*)q, (const float4*)k, (float4*)qr, (float4*)kr);
    prep_vt<<<dim3(S_DIM / 32, D_DIM / 32, B_DIM), dim3(32, 32)>>>(v, (float*)vt);

    cudaFuncSetAttribute(attn_main, cudaFuncAttributeMaxDynamicSharedMemorySize, SMEM_BYTES);
    attn_main<<<B_DIM * 16, 512, SMEM_BYTES>>>(qmap, kmap, vmap,
                                               (const unsigned long long*)mbp, out);
}

// round 10
// speedup vs baseline: 1.0773x; 1.0194x over previous
#include <cuda_runtime.h>
#include <cuda.h>
#include <cstdint>
#include <cstddef>

// ---------------------------------------------------------------------------
// Problem constants
// ---------------------------------------------------------------------------
#define B_DIM 16
#define S_DIM 2048
#define D_DIM 128
#define NT2 32            // 64-row k-tiles

// exp(x) = exp2(x*log2e); fold log2e/sqrt(128) into Q pre-scale
#define CQ_SCALE ((float)(1.4426950408889634 / 11.313708498984761))

// SMEM layout: [0,512) rowsum f32[128]; [512..544) mbarriers; buffers at 1024
// QBUF 64K | KB0 32K | KB1 32K | VB0 32K | VB1 32K | PBUF 32K
#define QBUF_OFF 1024
#define KB0_OFF  (1024 + 65536)
#define KB1_OFF  (KB0_OFF + 32768)
#define VB0_OFF  (KB1_OFF + 32768)
#define VB1_OFF  (VB0_OFF + 32768)
#define PBUF_OFF (VB1_OFF + 32768)
#define SMEM_BYTES (PBUF_OFF + 32768)   // 230400

// ---------------------------------------------------------------------------
// Device scratch (static; no allocations allowed)
// ---------------------------------------------------------------------------
__device__ float g_Qr[B_DIM * S_DIM * D_DIM];                 // Q*(log2e/sqrt d), tf32-rounded
__device__ float g_Kr[B_DIM * S_DIM * D_DIM];                 // K tf32-rounded
__device__ float g_VT[B_DIM * D_DIM * S_DIM];                 // V^T [b][d][s], tf32-rounded
__device__ unsigned long long g_Mb[B_DIM * S_DIM * (S_DIM / 64)];  // mask bitpack

// ---------------------------------------------------------------------------
// PTX helpers
// ---------------------------------------------------------------------------
__device__ __forceinline__ uint32_t smem_u32(const void* p) {
    uint32_t a;
    asm("{ .reg .u64 t; cvta.to.shared.u64 t, %1; cvt.u32.u64 %0, t; }" : "=r"(a) : "l"(p));
    return a;
}
// cvt.rna.tf32.f32 requires a .b32 destination register.
__device__ __forceinline__ float rna_tf32(float x) {
    uint32_t r; asm("cvt.rna.tf32.f32 %0, %1;" : "=r"(r) : "f"(x));
    return __uint_as_float(r);
}
__device__ __forceinline__ float ex2f(float x) {
    float r; asm("ex2.approx.f32 %0, %1;" : "=f"(r) : "f"(x)); return r;
}

#define MBAR_INIT(a, c) \
    asm volatile("mbarrier.init.shared.b64 [%0], %1;" :: "r"(a), "r"((uint32_t)(c)) : "memory")
#define MBAR_EXPECT_TX(a, n) \
    asm volatile("mbarrier.arrive.expect_tx.shared.b64 _, [%0], %1;" :: "r"(a), "r"((uint32_t)(n)) : "memory")

#define MBAR_WAIT(a, ph) do {                                                     \
    uint32_t _m = (a), _p = (uint32_t)(ph), _d;                                   \
    asm volatile("{\n\t.reg .pred p;\n\t"                                         \
        "mbarrier.try_wait.parity.acquire.cta.shared::cta.b64 p, [%1], %2;\n\t"   \
        "selp.b32 %0, 1, 0, p;\n\t}"                                              \
        : "=r"(_d) : "r"(_m), "r"(_p) : "memory");                                \
    if (!_d) {                                                                    \
        asm volatile("{\n\t.reg .pred P1;\n\t"                                    \
            "WL_%=:\n\t"                                                          \
            "mbarrier.try_wait.parity.acquire.cta.shared::cta.b64 P1, [%0], %1, 0x989680;\n\t" \
            "@P1 bra.uni WD_%=;\n\t"                                              \
            "bra.uni WL_%=;\n\t"                                                  \
            "WD_%=:\n\t}"                                                         \
            :: "r"(_m), "r"(_p) : "memory");                                      \
    }                                                                             \
} while (0)

// Pairwise named barrier: 64 threads (warps mchunk and mchunk+8)
#define PAIR_BAR(id) \
    asm volatile("bar.sync %0, 64;" :: "r"((uint32_t)(id)) : "memory")

#define TMA3D(dst, map, x, y, z, mb)                                              \
    asm volatile("cp.async.bulk.tensor.3d.shared::cta.global.tile.mbarrier::complete_tx::bytes " \
                 "[%0], [%1, {%2, %3, %4}], [%5];"                                \
                 :: "r"(dst), "l"(map), "r"((int)(x)), "r"((int)(y)), "r"((int)(z)), "r"(mb) : "memory")

// Swizzled address of f32 element (row, col): region = 32 f32-cols wide,
// rows*128B tall; rshift = log2(region bytes). TMA SW128 swizzle inside.
__device__ __forceinline__ uint32_t swa2(uint32_t buf, int row, int col, int rshift) {
    uint32_t byte = (uint32_t)(row * 128 + (col & 31) * 4);
    return buf + (((uint32_t)col >> 5) << rshift) + (byte ^ ((byte >> 3) & 0x70));
}

__device__ __forceinline__ void ldsm4(uint32_t addr, uint32_t* r) {
    asm volatile("ldmatrix.sync.aligned.m8n8.x4.shared.b16 {%0,%1,%2,%3}, [%4];"
                 : "=r"(r[0]), "=r"(r[1]), "=r"(r[2]), "=r"(r[3]) : "r"(addr));
}

__device__ __forceinline__ void mma8(float* c, const uint32_t* a, uint32_t b0, uint32_t b1) {
    asm volatile("mma.sync.aligned.m16n8k8.row.col.f32.tf32.tf32.f32 "
                 "{%0,%1,%2,%3}, {%4,%5,%6,%7}, {%8,%9}, {%0,%1,%2,%3};"
                 : "+f"(c[0]), "+f"(c[1]), "+f"(c[2]), "+f"(c[3])
                 : "r"(a[0]), "r"(a[1]), "r"(a[2]), "r"(a[3]), "r"(b0), "r"(b1));
}

__device__ __forceinline__ void sts2(uint32_t addr, float x, float y) {
    asm volatile("st.shared.v2.f32 [%0], {%1,%2};" :: "r"(addr), "f"(x), "f"(y) : "memory");
}

// ---------------------------------------------------------------------------
// Prep kernels
// ---------------------------------------------------------------------------
__global__ void prep_qk(const float4* __restrict__ q, const float4* __restrict__ k,
                        float4* __restrict__ qo, float4* __restrict__ ko) {
    int i = blockIdx.x * blockDim.x + threadIdx.x;
    float4 a = q[i];
    a.x = rna_tf32(a.x * CQ_SCALE); a.y = rna_tf32(a.y * CQ_SCALE);
    a.z = rna_tf32(a.z * CQ_SCALE); a.w = rna_tf32(a.w * CQ_SCALE);
    qo[i] = a;
    float4 b = k[i];
    b.x = rna_tf32(b.x); b.y = rna_tf32(b.y);
    b.z = rna_tf32(b.z); b.w = rna_tf32(b.w);
    ko[i] = b;
}

__global__ void prep_vt(const float* __restrict__ v, float* __restrict__ vt) {
    __shared__ float t[32][33];
    int b = blockIdx.z;
    int s0 = blockIdx.x * 32, d0 = blockIdx.y * 32;
    const float* vb = v + (size_t)b * S_DIM * D_DIM;
    float* vtb = vt + (size_t)b * D_DIM * S_DIM;
    t[threadIdx.y][threadIdx.x] =
        rna_tf32(vb[(size_t)(s0 + threadIdx.y) * D_DIM + d0 + threadIdx.x]);
    __syncthreads();
    vtb[(size_t)(d0 + threadIdx.y) * S_DIM + s0 + threadIdx.x] = t[threadIdx.x][threadIdx.y];
}

// Mask arrives as 4-byte elements (verified in R7 profile: 264MB DRAM read).
// out byte i <- mask elements [8i, 8i+8); bit j of byte i = element 8i+j.
__global__ void prep_mask(const uint4* __restrict__ m, unsigned char* __restrict__ o) {
    int i = blockIdx.x * blockDim.x + threadIdx.x;
    const uint4* p = m + (size_t)i * 2;
    uint4 a = p[0], b = p[1];
    unsigned v =
        (a.x != 0u ? 1u : 0u) | (a.y != 0u ? 2u : 0u) |
        (a.z != 0u ? 4u : 0u) | (a.w != 0u ? 8u : 0u) |
        (b.x != 0u ? 16u : 0u) | (b.y != 0u ? 32u : 0u) |
        (b.z != 0u ? 64u : 0u) | (b.w != 0u ? 128u : 0u);
    o[i] = (unsigned char)v;
}

// ---------------------------------------------------------------------------
// Main fused attention kernel — double-buffered 64-row k-tiles, 16 warps.
// 1 CTA = (batch, 128-row q-tile); warp: mchunk = wid&7 (16 q-rows),
// half = wid>>3. S-phase: warp = 16m x 32n. O-phase: warp = 16m x 64d.
// Sync scheme: ONE full __syncthreads per tile (post-S; protects K/V TMA
// overwrite + P overwrite), plus ONE pairwise bar.sync (P visibility
// between the two warps sharing an m-chunk). Pairs flow independently.
// ---------------------------------------------------------------------------
__global__ void __launch_bounds__(512, 1) attn_main(
    const __grid_constant__ CUtensorMap qmap,
    const __grid_constant__ CUtensorMap kmap,   // box {32,64}
    const __grid_constant__ CUtensorMap vmap,   // box {32,128}
    const unsigned long long* __restrict__ mbits,
    float* __restrict__ out)
{
    extern __shared__ char smem[];
    float* rs = (float*)smem;               // rowsum[128]
    const uint32_t sb = smem_u32(smem);
    const uint32_t kbar0 = sb + 512, kbar1 = sb + 520;
    const uint32_t vbar0 = sb + 528, vbar1 = sb + 536;
    const uint32_t QBUF = sb + QBUF_OFF, PBUF = sb + PBUF_OFF;
    const uint32_t KB[2] = {sb + KB0_OFF, sb + KB1_OFF};
    const uint32_t VB[2] = {sb + VB0_OFF, sb + VB1_OFF};

    const int tid = threadIdx.x, wid = tid >> 5, lane = tid & 31;
    const int mchunk = wid & 7, half = wid >> 3;
    const int tig = lane & 3, g = lane >> 2;
    const int b = blockIdx.x >> 4, qt = blockIdx.x & 15;

    // ldmatrix lane-role rows
    const int arow0  = 16 * mchunk + (lane & 7) + ((lane >> 3) & 1) * 8;  // A rows (one m16 tile)
    const int brow_s = 32 * half + (lane & 7) + ((lane >> 4) & 1) * 8;    // S-phase B (+16*nbp, nbp<2)
    const int brow_o = 64 * half + (lane & 7) + ((lane >> 4) & 1) * 8;    // O-phase B (+16*nbp, nbp<4)
    const int acsel = ((lane >> 4) & 1) * 4;
    const int bcsel = ((lane >> 3) & 1) * 4;

    if (tid < 128) rs[tid] = 0.0f;
    if (tid == 0) {
        MBAR_INIT(kbar0, 1); MBAR_INIT(kbar1, 1);
        MBAR_INIT(vbar0, 1); MBAR_INIT(vbar1, 1);
    }
    __syncthreads();

    // Prologue: Q + K(0) on kbar0; V(0) on vbar0; K(1)/V(1) prefetch on bar1
    if (tid == 0) {
        MBAR_EXPECT_TX(kbar0, 65536 + 32768);
#pragma unroll
        for (int c = 0; c < 4; c++) {
            TMA3D(QBUF + c * 16384, &qmap, 32 * c, qt * 128, b, kbar0);
            TMA3D(KB[0] + c * 8192, &kmap, 32 * c, 0, b, kbar0);
        }
        MBAR_EXPECT_TX(vbar0, 32768);
#pragma unroll
        for (int c = 0; c < 2; c++)
            TMA3D(VB[0] + c * 16384, &vmap, 32 * c, 0, b, vbar0);
    }

    float oacc[8][4];
#pragma unroll
    for (int nb = 0; nb < 8; nb++)
#pragma unroll
        for (int i = 0; i < 4; i++) oacc[nb][i] = 0.0f;

    float rsum[2] = {0.f, 0.f};
    const size_t mrow_base = ((size_t)b * S_DIM + qt * 128) * (S_DIM / 64);
    const int r0m = 16 * mchunk + g;

    for (int j = 0; j < NT2; j++) {
        const int bi = j & 1, ni = bi ^ 1;
        const int ph = (j >> 1) & 1;                  // parity of both bars at tile j
        const uint32_t kb = bi ? kbar1 : kbar0;
        const uint32_t vb = bi ? vbar1 : vbar0;

        // Mask u64s (issued before barrier wait to hide latency)
        unsigned long long mrow0 = __ldg(mbits + mrow_base + (size_t)r0m * 32 + j);
        unsigned long long mrow1 = __ldg(mbits + mrow_base + (size_t)(r0m + 8) * 32 + j);

        MBAR_WAIT(kb, ph);

        // ---- S-phase: S(128x64) = Q @ K(j)^T over d (16 k8-steps) ----
        float sacc[4][4];
#pragma unroll
        for (int nb = 0; nb < 4; nb++)
#pragma unroll
            for (int i = 0; i < 4; i++) sacc[nb][i] = 0.0f;

#pragma unroll 8
        for (int kk = 0; kk < 16; kk++) {
            uint32_t a0[4], bb[2][4];
            ldsm4(swa2(QBUF, arow0, 8 * kk + acsel, 14), a0);
#pragma unroll
            for (int nbp = 0; nbp < 2; nbp++)
                ldsm4(swa2(KB[bi], brow_s + 16 * nbp, 8 * kk + bcsel, 13), bb[nbp]);
#pragma unroll
            for (int nbp = 0; nbp < 2; nbp++) {
                mma8(sacc[2 * nbp],     a0, bb[nbp][0], bb[nbp][1]);
                mma8(sacc[2 * nbp + 1], a0, bb[nbp][2], bb[nbp][3]);
            }
        }

        // ---- Full CTA rendezvous: all warps finished S(j) (hence O(j-1)).
        // Safe point for TMA overwrite of KB[ni]/VB[ni] and P overwrite below.
        __syncthreads();
        if (tid == 0 && j < NT2 - 1) {
            const uint32_t kbn = ni ? kbar1 : kbar0;
            const uint32_t vbn = ni ? vbar1 : vbar0;
            MBAR_EXPECT_TX(kbn, 32768);
#pragma unroll
            for (int c = 0; c < 4; c++)
                TMA3D(KB[ni] + c * 8192, &kmap, 32 * c, (j + 1) * 64, b, kbn);
            MBAR_EXPECT_TX(vbn, 32768);
#pragma unroll
            for (int c = 0; c < 2; c++)
                TMA3D(VB[ni] + c * 16384, &vmap, (j + 1) * 64 + 32 * c, 0, b, vbn);
        }

        // ---- exp + mask; write P (tf32-rounded) into PBUF; row-sum ----
#pragma unroll
        for (int nb = 0; nb < 4; nb++) {
            float* c = sacc[nb];
            unsigned sh = 32 * half + 8 * nb + 2 * tig;
            unsigned m0 = (unsigned)(mrow0 >> sh) & 3u;
            unsigned m1 = (unsigned)(mrow1 >> sh) & 3u;
            float p0 = (m0 & 1u) ? 0.f : rna_tf32(ex2f(c[0]));
            float p1 = (m0 & 2u) ? 0.f : rna_tf32(ex2f(c[1]));
            float p2 = (m1 & 1u) ? 0.f : rna_tf32(ex2f(c[2]));
            float p3 = (m1 & 2u) ? 0.f : rna_tf32(ex2f(c[3]));
            rsum[0] += p0 + p1;
            rsum[1] += p2 + p3;
            int cl = 32 * half + 8 * nb + 2 * tig;
            sts2(swa2(PBUF, r0m,     cl, 14), p0, p1);
            sts2(swa2(PBUF, r0m + 8, cl, 14), p2, p3);
        }
        // P-halves exchange within the m-chunk pair only
        PAIR_BAR(1 + mchunk);

        MBAR_WAIT(vb, ph);

        // ---- O-phase: O(128x128) += P(128x64) @ V(j)(64x128) ----
#pragma unroll 4
        for (int kk = 0; kk < 8; kk++) {
            uint32_t a0[4], bb[4][4];
            ldsm4(swa2(PBUF, arow0, 8 * kk + acsel, 14), a0);
#pragma unroll
            for (int nbp = 0; nbp < 4; nbp++)
                ldsm4(swa2(VB[bi], brow_o + 16 * nbp, 8 * kk + bcsel, 14), bb[nbp]);
#pragma unroll
            for (int nbp = 0; nbp < 4; nbp++) {
                mma8(oacc[2 * nbp],     a0, bb[nbp][0], bb[nbp][1]);
                mma8(oacc[2 * nbp + 1], a0, bb[nbp][2], bb[nbp][3]);
            }
        }
        // no end-of-tile sync: next tile's post-S __syncthreads covers reuse
    }

    // ---- Row sums: reduce over tig, combine halves via smem atomics ----
    rsum[0] += __shfl_xor_sync(0xffffffffu, rsum[0], 1);
    rsum[0] += __shfl_xor_sync(0xffffffffu, rsum[0], 2);
    rsum[1] += __shfl_xor_sync(0xffffffffu, rsum[1], 1);
    rsum[1] += __shfl_xor_sync(0xffffffffu, rsum[1], 2);
    if (tig == 0) {
        atomicAdd(&rs[r0m],     rsum[0]);
        atomicAdd(&rs[r0m + 8], rsum[1]);
    }
    __syncthreads();

    // ---- Normalize + store O ----
    const size_t obase = ((size_t)b * S_DIM + qt * 128) * D_DIM;
    {
        float inv0 = 1.0f / rs[r0m];
        float inv1 = 1.0f / rs[r0m + 8];
#pragma unroll
        for (int di = 0; di < 8; di++) {
            int col = 64 * half + 8 * di + 2 * tig;
            float* c = oacc[di];
            float2* p0 = (float2*)(out + obase + (size_t)r0m * D_DIM + col);
            float2* p1 = (float2*)(out + obase + (size_t)(r0m + 8) * D_DIM + col);
            *p0 = make_float2(c[0] * inv0, c[1] * inv0);
            *p1 = make_float2(c[2] * inv1, c[3] * inv1);
        }
    }
}

// ---------------------------------------------------------------------------
// Host launcher
// ---------------------------------------------------------------------------
typedef CUresult (*EncodeFn)(CUtensorMap*, CUtensorMapDataType, cuuint32_t, void*,
                             const cuuint64_t*, const cuuint64_t*, const cuuint32_t*,
                             const cuuint32_t*, CUtensorMapInterleave, CUtensorMapSwizzle,
                             CUtensorMapL2promotion, CUtensorMapFloatOOBfill);

static void make_map(EncodeFn enc, CUtensorMap* m, void* ptr,
                     cuuint64_t d0, cuuint64_t d1, cuuint64_t d2, cuuint32_t box1) {
    cuuint64_t dims[3] = {d0, d1, d2};
    cuuint64_t strides[2] = {d0 * 4, d0 * d1 * 4};
    cuuint32_t box[3] = {32, box1, 1};
    cuuint32_t es[3] = {1, 1, 1};
    enc(m, CU_TENSOR_MAP_DATA_TYPE_FLOAT32, 3, ptr, dims, strides, box, es,
        CU_TENSOR_MAP_INTERLEAVE_NONE, CU_TENSOR_MAP_SWIZZLE_128B,
        CU_TENSOR_MAP_L2_PROMOTION_L2_128B, CU_TENSOR_MAP_FLOAT_OOB_FILL_NONE);
}

extern "C" void kernel_launch(void* const* d_in, const int* in_sizes, int n_in,
                              void* d_out, int out_size) {
    const float* q = (const float*)d_in[0];
    const float* k = (const float*)d_in[1];
    const float* v = (const float*)d_in[2];
    const void* mask = d_in[3];
    float* out = (float*)d_out;

    void *qr = 0, *kr = 0, *vt = 0, *mbp = 0;
    cudaGetSymbolAddress(&qr, g_Qr);
    cudaGetSymbolAddress(&kr, g_Kr);
    cudaGetSymbolAddress(&vt, g_VT);
    cudaGetSymbolAddress(&mbp, g_Mb);

    void* fptr = 0;
    cudaDriverEntryPointQueryResult qres;
    cudaGetDriverEntryPointByVersion("cuTensorMapEncodeTiled", &fptr, 12000,
                                     cudaEnableDefault, &qres);
    EncodeFn enc = (EncodeFn)fptr;
    if (!enc) return;

    CUtensorMap qmap, kmap, vmap;
    make_map(enc, &qmap, qr, D_DIM, S_DIM, B_DIM, 128);  // Q: box 32d x 128s
    make_map(enc, &kmap, kr, D_DIM, S_DIM, B_DIM, 64);   // K: box 32d x 64s
    make_map(enc, &vmap, vt, S_DIM, D_DIM, B_DIM, 128);  // V^T: box 32s x 128d

    // Prep passes (3 before attn_main so ncu's capture slot lands on attn_main)
    int nmb = (B_DIM * S_DIM * S_DIM) / 8;                // 8,388,608 output bytes
    prep_mask<<<nmb / 256, 256>>>((const uint4*)mask, (unsigned char*)mbp);
    int n4 = (B_DIM * S_DIM * D_DIM) / 4;                 // 1,048,576
    prep_qk<<<n4 / 256, 256>>>((const float4*)q, (const float4*)k, (float4*)qr, (float4*)kr);
    prep_vt<<<dim3(S_DIM / 32, D_DIM / 32, B_DIM), dim3(32, 32)>>>(v, (float*)vt);

    cudaFuncSetAttribute(attn_main, cudaFuncAttributeMaxDynamicSharedMemorySize, SMEM_BYTES);
    attn_main<<<B_DIM * 16, 512, SMEM_BYTES>>>(qmap, kmap, vmap,
                                               (const unsigned long long*)mbp, out);
}